// round 1
// baseline (speedup 1.0000x reference)
#include <cuda_runtime.h>
#include <math.h>

#define B_DIM 2
#define NUM_HEADS 32
#define NUM_KV 8
#define SEQ 2048
#define DM 2048
#define HD 64

// Scratch (allocation-free: device globals)
__device__ float g_q[(size_t)B_DIM * NUM_HEADS * SEQ * HD];   // [B,H,S,D]  32MB
__device__ float g_k[(size_t)B_DIM * NUM_KV   * SEQ * HD];    // [B,KV,S,D]  8MB
__device__ float g_v[(size_t)B_DIM * NUM_KV   * SEQ * HD];    // [B,KV,S,D]  8MB
__device__ float g_ao[(size_t)B_DIM * SEQ * DM];              // [B,S,H*D]  32MB

// ---------------------------------------------------------------------------
// SGEMM 128x128x8, 256 threads, 8x8 per-thread tile, fused epilogues:
// mode 0: C[m*N+n] = acc                       (final Wo projection)
// mode 1: RoPE + transpose into g_q            (Q projection)
// mode 2: RoPE + transpose into g_k            (K projection)
// mode 3: transpose into g_v                   (V projection)
// ---------------------------------------------------------------------------
#define BM 128
#define BN 128
#define BK 8

__global__ __launch_bounds__(256) void sgemm_ep(
    const float* __restrict__ A, const float* __restrict__ B,
    float* __restrict__ C, int M, int N, int K, int mode)
{
    __shared__ float As[BK][BM];
    __shared__ float Bs[BK][BN];

    const int tid = threadIdx.x;
    const int m0 = blockIdx.y * BM;
    const int n0 = blockIdx.x * BN;
    const int ty = tid >> 4;        // 0..15
    const int tx = tid & 15;        // 0..15

    float acc[8][8];
#pragma unroll
    for (int i = 0; i < 8; i++)
#pragma unroll
        for (int j = 0; j < 8; j++) acc[i][j] = 0.f;

    const int a_r = tid >> 1;          // 0..127
    const int a_c = (tid & 1) * 4;     // 0 or 4
    const int b_r = tid >> 5;          // 0..7
    const int b_c = (tid & 31) * 4;    // 0..124

    for (int kt = 0; kt < K; kt += BK) {
        float4 av = *(const float4*)&A[(size_t)(m0 + a_r) * K + kt + a_c];
        float4 bv = *(const float4*)&B[(size_t)(kt + b_r) * N + n0 + b_c];
        As[a_c + 0][a_r] = av.x;
        As[a_c + 1][a_r] = av.y;
        As[a_c + 2][a_r] = av.z;
        As[a_c + 3][a_r] = av.w;
        *(float4*)&Bs[b_r][b_c] = bv;
        __syncthreads();

#pragma unroll
        for (int k = 0; k < BK; k++) {
            float af[8], bf[8];
            *(float4*)&af[0] = *(float4*)&As[k][ty * 8];
            *(float4*)&af[4] = *(float4*)&As[k][ty * 8 + 4];
            *(float4*)&bf[0] = *(float4*)&Bs[k][tx * 8];
            *(float4*)&bf[4] = *(float4*)&Bs[k][tx * 8 + 4];
#pragma unroll
            for (int i = 0; i < 8; i++)
#pragma unroll
                for (int j = 0; j < 8; j++)
                    acc[i][j] = fmaf(af[i], bf[j], acc[i][j]);
        }
        __syncthreads();
    }

    if (mode == 0) {
#pragma unroll
        for (int i = 0; i < 8; i++) {
            int m = m0 + ty * 8 + i;
            float4 w0 = make_float4(acc[i][0], acc[i][1], acc[i][2], acc[i][3]);
            float4 w1 = make_float4(acc[i][4], acc[i][5], acc[i][6], acc[i][7]);
            *(float4*)&C[(size_t)m * N + n0 + tx * 8] = w0;
            *(float4*)&C[(size_t)m * N + n0 + tx * 8 + 4] = w1;
        }
        return;
    }

    // RoPE + transpose epilogues
    const float LOGC = 0.28782313662425572f;  // ln(10000)/32
#pragma unroll
    for (int i = 0; i < 8; i++) {
        int m = m0 + ty * 8 + i;
        int b = m >> 11;          // / SEQ
        int s = m & (SEQ - 1);
        float fs = (float)s;
#pragma unroll
        for (int j = 0; j < 8; j += 2) {
            int n = n0 + tx * 8 + j;
            int h = n >> 6;           // head index in this projection's width
            int d0 = n & 63;          // even
            float x0 = acc[i][j], x1 = acc[i][j + 1];
            float o0, o1;
            if (mode == 3) {
                o0 = x0; o1 = x1;
            } else {
                int j0 = d0 & 31;
                int j1 = (d0 + 1) & 31;
                float inv0 = expf(-(float)j0 * LOGC);
                float inv1 = expf(-(float)j1 * LOGC);
                float s0, c0, s1, c1;
                sincosf(fs * inv0, &s0, &c0);
                sincosf(fs * inv1, &s1, &c1);
                o0 = x0 * c0 - x1 * s0;
                o1 = x1 * c1 + x0 * s1;
            }
            float* dst;
            if (mode == 1)
                dst = &g_q[(((size_t)b * NUM_HEADS + h) * SEQ + s) * HD + d0];
            else if (mode == 2)
                dst = &g_k[(((size_t)b * NUM_KV + h) * SEQ + s) * HD + d0];
            else
                dst = &g_v[(((size_t)b * NUM_KV + h) * SEQ + s) * HD + d0];
            dst[0] = o0;
            dst[1] = o1;
        }
    }
}

// ---------------------------------------------------------------------------
// Flash attention: 64 queries x 64 keys per tile, d=64, causal, online softmax.
// 256 threads, thread grid 16x16, each thread owns 4x4 score / 4x4 O tile.
// Dynamic shared: q_s[d][r], k_s[d][c], v_s[kk][d], p_s[r][kk]  (64KB)
// ---------------------------------------------------------------------------
__global__ __launch_bounds__(256) void flash_attn()
{
    extern __shared__ float sm[];
    float* q_s = sm;             // [64][64]  (d-major)
    float* k_s = sm + 4096;      // [64][64]  (d-major)
    float* v_s = sm + 8192;      // [64][64]  (key-major)
    float* p_s = sm + 12288;     // [64][64]  (row-major)

    const int tid = threadIdx.x;
    const int ty = tid >> 4;     // 0..15 -> rows ty*4..+3
    const int tx = tid & 15;     // 0..15 -> cols tx*4..+3
    const int qs = blockIdx.x * 64;
    const int h  = blockIdx.y;
    const int b  = blockIdx.z;
    const int kvh = h >> 2;

    const float* qg = &g_q[(((size_t)b * NUM_HEADS + h) * SEQ + qs) * HD];
    const float* kg = &g_k[(((size_t)b * NUM_KV + kvh) * SEQ) * HD];
    const float* vg = &g_v[(((size_t)b * NUM_KV + kvh) * SEQ) * HD];

    // Load Q tile, transposed to d-major
    {
        int r = tid >> 2;
        int c = (tid & 3) * 16;
#pragma unroll
        for (int u = 0; u < 4; u++) {
            float4 v4 = *(const float4*)&qg[r * 64 + c + u * 4];
            q_s[(c + u * 4 + 0) * 64 + r] = v4.x;
            q_s[(c + u * 4 + 1) * 64 + r] = v4.y;
            q_s[(c + u * 4 + 2) * 64 + r] = v4.z;
            q_s[(c + u * 4 + 3) * 64 + r] = v4.w;
        }
    }

    float m_i[4], l_i[4], acc[4][4];
#pragma unroll
    for (int i = 0; i < 4; i++) {
        m_i[i] = -1e30f;
        l_i[i] = 0.f;
#pragma unroll
        for (int j = 0; j < 4; j++) acc[i][j] = 0.f;
    }

    const float scale = 0.125f;  // 1/sqrt(64)

    for (int kt = 0; kt <= qs; kt += 64) {
        __syncthreads();  // prior PV done before overwriting k_s/v_s
        {
            int r = tid >> 2;
            int c = (tid & 3) * 16;
#pragma unroll
            for (int u = 0; u < 4; u++) {
                float4 kv4 = *(const float4*)&kg[(size_t)(kt + r) * 64 + c + u * 4];
                k_s[(c + u * 4 + 0) * 64 + r] = kv4.x;
                k_s[(c + u * 4 + 1) * 64 + r] = kv4.y;
                k_s[(c + u * 4 + 2) * 64 + r] = kv4.z;
                k_s[(c + u * 4 + 3) * 64 + r] = kv4.w;
                float4 vv4 = *(const float4*)&vg[(size_t)(kt + r) * 64 + c + u * 4];
                *(float4*)&v_s[r * 64 + c + u * 4] = vv4;
            }
        }
        __syncthreads();

        // S = Q @ K^T  (4x4 per thread)
        float sreg[4][4];
#pragma unroll
        for (int i = 0; i < 4; i++)
#pragma unroll
            for (int j = 0; j < 4; j++) sreg[i][j] = 0.f;

#pragma unroll 16
        for (int kd = 0; kd < 64; kd++) {
            float4 qf = *(float4*)&q_s[kd * 64 + ty * 4];
            float4 kf = *(float4*)&k_s[kd * 64 + tx * 4];
            float qa[4] = {qf.x, qf.y, qf.z, qf.w};
            float ka[4] = {kf.x, kf.y, kf.z, kf.w};
#pragma unroll
            for (int i = 0; i < 4; i++)
#pragma unroll
                for (int j = 0; j < 4; j++)
                    sreg[i][j] = fmaf(qa[i], ka[j], sreg[i][j]);
        }

        // scale + causal mask
#pragma unroll
        for (int i = 0; i < 4; i++) {
            int row = qs + ty * 4 + i;
#pragma unroll
            for (int j = 0; j < 4; j++) {
                int col = kt + tx * 4 + j;
                float v = sreg[i][j] * scale;
                sreg[i][j] = (col > row) ? -1e30f : v;
            }
        }

        // online softmax per row (reduce across 16 tx lanes)
#pragma unroll
        for (int i = 0; i < 4; i++) {
            float mx = fmaxf(fmaxf(sreg[i][0], sreg[i][1]),
                             fmaxf(sreg[i][2], sreg[i][3]));
#pragma unroll
            for (int off = 8; off >= 1; off >>= 1)
                mx = fmaxf(mx, __shfl_xor_sync(0xffffffffu, mx, off));
            float mnew = fmaxf(m_i[i], mx);
            float alpha = __expf(m_i[i] - mnew);
            float ps = 0.f;
#pragma unroll
            for (int j = 0; j < 4; j++) {
                float p = __expf(sreg[i][j] - mnew);
                sreg[i][j] = p;
                ps += p;
            }
#pragma unroll
            for (int off = 8; off >= 1; off >>= 1)
                ps += __shfl_xor_sync(0xffffffffu, ps, off);
            l_i[i] = l_i[i] * alpha + ps;
            m_i[i] = mnew;
#pragma unroll
            for (int j = 0; j < 4; j++) acc[i][j] *= alpha;
            *(float4*)&p_s[(ty * 4 + i) * 64 + tx * 4] =
                make_float4(sreg[i][0], sreg[i][1], sreg[i][2], sreg[i][3]);
        }
        __syncthreads();

        // O += P @ V
#pragma unroll 8
        for (int kk = 0; kk < 64; kk++) {
            float4 vf = *(float4*)&v_s[kk * 64 + tx * 4];
#pragma unroll
            for (int i = 0; i < 4; i++) {
                float p = p_s[(ty * 4 + i) * 64 + kk];
                acc[i][0] = fmaf(p, vf.x, acc[i][0]);
                acc[i][1] = fmaf(p, vf.y, acc[i][1]);
                acc[i][2] = fmaf(p, vf.z, acc[i][2]);
                acc[i][3] = fmaf(p, vf.w, acc[i][3]);
            }
        }
    }

    // epilogue: normalize, write to [B,S,H*D]
    float* og = &g_ao[((size_t)b * SEQ + qs) * DM + h * HD];
#pragma unroll
    for (int i = 0; i < 4; i++) {
        float inv = 1.f / l_i[i];
        float4 o = make_float4(acc[i][0] * inv, acc[i][1] * inv,
                               acc[i][2] * inv, acc[i][3] * inv);
        *(float4*)&og[(size_t)(ty * 4 + i) * DM + tx * 4] = o;
    }
}

// ---------------------------------------------------------------------------

extern "C" void kernel_launch(void* const* d_in, const int* in_sizes, int n_in,
                              void* d_out, int out_size)
{
    const float* x  = (const float*)d_in[0];
    // d_in[1] = mask (deterministic causal tril; not needed)
    const float* Wq = (const float*)d_in[2];
    const float* Wk = (const float*)d_in[3];
    const float* Wv = (const float*)d_in[4];
    const float* Wo = (const float*)d_in[5];
    float* out = (float*)d_out;

    const int M = B_DIM * SEQ;  // 4096

    cudaFuncSetAttribute(flash_attn, cudaFuncAttributeMaxDynamicSharedMemorySize,
                         64 * 1024);

    dim3 blk(256);
    // Q projection + RoPE + transpose
    sgemm_ep<<<dim3(DM / BN, M / BM), blk>>>(x, Wq, nullptr, M, DM, DM, 1);
    // K projection + RoPE + transpose
    sgemm_ep<<<dim3((NUM_KV * HD) / BN, M / BM), blk>>>(x, Wk, nullptr, M, NUM_KV * HD, DM, 2);
    // V projection + transpose
    sgemm_ep<<<dim3((NUM_KV * HD) / BN, M / BM), blk>>>(x, Wv, nullptr, M, NUM_KV * HD, DM, 3);

    // Causal flash attention
    flash_attn<<<dim3(SEQ / 64, NUM_HEADS, B_DIM), blk, 64 * 1024>>>();

    // Output projection
    void* aoPtr = nullptr;
    cudaGetSymbolAddress(&aoPtr, g_ao);
    sgemm_ep<<<dim3(DM / BN, M / BM), blk>>>((const float*)aoPtr, Wo, out, M, DM, DM, 0);
}

// round 2
// speedup vs baseline: 1.8298x; 1.8298x over previous
#include <cuda_runtime.h>
#include <math.h>
#include <stdint.h>

#define B_DIM 2
#define NUM_HEADS 32
#define NUM_KV 8
#define SEQ 2048
#define DM 2048
#define HD 64

// Scratch (allocation-free: device globals)
__device__ float g_q[(size_t)B_DIM * NUM_HEADS * SEQ * HD];   // [B,H,S,D]
__device__ float g_k[(size_t)B_DIM * NUM_KV   * SEQ * HD];    // [B,KV,S,D]
__device__ float g_v[(size_t)B_DIM * NUM_KV   * SEQ * HD];    // [B,KV,S,D]
__device__ float g_ao[(size_t)B_DIM * SEQ * DM];              // [B,S,H*D]
__device__ float g_rope[(size_t)SEQ * 32 * 2];                // (cos,sin) per (s, j)

// ---------------------------------------------------------------------------
// RoPE table precompute: angle(s, j) = s * 10000^(-j/32), j in [0,32)
// ---------------------------------------------------------------------------
__global__ void rope_init()
{
    int i = blockIdx.x * blockDim.x + threadIdx.x;   // SEQ*32 threads
    int s = i >> 5, j = i & 31;
    float inv = expf(-(float)j * 0.28782313662425572f);  // ln(10000)/32
    float sv, cv;
    sincosf((float)s * inv, &sv, &cv);
    g_rope[(size_t)i * 2 + 0] = cv;
    g_rope[(size_t)i * 2 + 1] = sv;
}

// ---------------------------------------------------------------------------
// tf32 tensor-core GEMM, 128x128 CTA tile, BK=16, 4 warps (each 64x64),
// double-buffered smem, RN tf32 conversion on the store side.
// mode 0: C = A@B      mode 1: RoPE+transpose -> g_q
// mode 2: RoPE+transpose -> g_k               mode 3: transpose -> g_v
// ---------------------------------------------------------------------------
#define AS_STRIDE 20
#define BS_STRIDE 136

__device__ __forceinline__ float to_tf32(float x)
{
    float r;
    asm("cvt.rna.tf32.f32 %0, %1;" : "=f"(r) : "f"(x));
    return r;
}

__device__ __forceinline__ void mma_tf32(float* c, const uint32_t* a, const uint32_t* b)
{
    asm volatile(
        "mma.sync.aligned.m16n8k8.row.col.f32.tf32.tf32.f32 "
        "{%0,%1,%2,%3}, {%4,%5,%6,%7}, {%8,%9}, {%0,%1,%2,%3};\n"
        : "+f"(c[0]), "+f"(c[1]), "+f"(c[2]), "+f"(c[3])
        : "r"(a[0]), "r"(a[1]), "r"(a[2]), "r"(a[3]), "r"(b[0]), "r"(b[1]));
}

__global__ __launch_bounds__(128) void gemm_tc(
    const float* __restrict__ A, const float* __restrict__ Bm,
    float* __restrict__ C, int M, int N, int K, int mode)
{
    __shared__ float As[2][128 * AS_STRIDE];
    __shared__ float Bs[2][16 * BS_STRIDE];

    const int tid = threadIdx.x;
    const int wid = tid >> 5, lane = tid & 31;
    const int wm = wid & 1, wn = wid >> 1;     // 2x2 warp grid
    const int g = lane >> 2, t = lane & 3;
    const int m0 = blockIdx.y * 128, n0 = blockIdx.x * 128;

    float acc[4][8][4];
#pragma unroll
    for (int mt = 0; mt < 4; mt++)
#pragma unroll
        for (int nt = 0; nt < 8; nt++)
#pragma unroll
            for (int r = 0; r < 4; r++) acc[mt][nt][r] = 0.f;

    float4 ra[4], rb[4];

    // global loads for tile at k-offset kt
    auto LDG = [&](int kt) {
#pragma unroll
        for (int u = 0; u < 4; u++) {
            int ca = tid + 128 * u;
            int rowa = ca >> 2, kq = ca & 3;
            ra[u] = *(const float4*)&A[(size_t)(m0 + rowa) * K + kt + kq * 4];
            int rowb = ca >> 5, nq = ca & 31;
            rb[u] = *(const float4*)&Bm[(size_t)(kt + rowb) * N + n0 + nq * 4];
        }
    };
    // cvt to tf32 (RN) + store to stage s
    auto STS = [&](int s) {
#pragma unroll
        for (int u = 0; u < 4; u++) {
            int ca = tid + 128 * u;
            int rowa = ca >> 2, kq = ca & 3;
            float4 va = make_float4(to_tf32(ra[u].x), to_tf32(ra[u].y),
                                    to_tf32(ra[u].z), to_tf32(ra[u].w));
            *(float4*)&As[s][rowa * AS_STRIDE + kq * 4] = va;
            int rowb = ca >> 5, nq = ca & 31;
            float4 vb = make_float4(to_tf32(rb[u].x), to_tf32(rb[u].y),
                                    to_tf32(rb[u].z), to_tf32(rb[u].w));
            *(float4*)&Bs[s][rowb * BS_STRIDE + nq * 4] = vb;
        }
    };

    LDG(0);
    STS(0);
    const int niter = K >> 4;

    for (int i = 0; i < niter; i++) {
        __syncthreads();
        if (i + 1 < niter) LDG((i + 1) << 4);
        const int s = i & 1;

#pragma unroll
        for (int kk = 0; kk < 2; kk++) {
            const int kb = kk * 8;
            uint32_t af[4][4], bf[8][2];
#pragma unroll
            for (int mt = 0; mt < 4; mt++) {
                int r = wm * 64 + mt * 16 + g;
                af[mt][0] = __float_as_uint(As[s][r * AS_STRIDE + kb + t]);
                af[mt][1] = __float_as_uint(As[s][(r + 8) * AS_STRIDE + kb + t]);
                af[mt][2] = __float_as_uint(As[s][r * AS_STRIDE + kb + t + 4]);
                af[mt][3] = __float_as_uint(As[s][(r + 8) * AS_STRIDE + kb + t + 4]);
            }
#pragma unroll
            for (int nt = 0; nt < 8; nt++) {
                int c = wn * 64 + nt * 8 + g;
                bf[nt][0] = __float_as_uint(Bs[s][(kb + t) * BS_STRIDE + c]);
                bf[nt][1] = __float_as_uint(Bs[s][(kb + t + 4) * BS_STRIDE + c]);
            }
#pragma unroll
            for (int mt = 0; mt < 4; mt++)
#pragma unroll
                for (int nt = 0; nt < 8; nt++)
                    mma_tf32(acc[mt][nt], af[mt], bf[nt]);
        }
        if (i + 1 < niter) {
            __syncthreads();
            STS((i + 1) & 1);
        }
    }

    // ---------------- epilogue ----------------
    if (mode == 0) {
#pragma unroll
        for (int mt = 0; mt < 4; mt++) {
            int row = m0 + wm * 64 + mt * 16 + g;
#pragma unroll
            for (int nt = 0; nt < 8; nt++) {
                int col = n0 + wn * 64 + nt * 8 + t * 2;
                *(float2*)&C[(size_t)row * N + col] =
                    make_float2(acc[mt][nt][0], acc[mt][nt][1]);
                *(float2*)&C[(size_t)(row + 8) * N + col] =
                    make_float2(acc[mt][nt][2], acc[mt][nt][3]);
            }
        }
        return;
    }

    // RoPE (+optional) transpose epilogue
#pragma unroll
    for (int mt = 0; mt < 4; mt++) {
#pragma unroll
        for (int half = 0; half < 2; half++) {
            int row = m0 + wm * 64 + mt * 16 + g + half * 8;
            int b = row >> 11;
            int sp = row & (SEQ - 1);
#pragma unroll
            for (int nt = 0; nt < 8; nt++) {
                int col = n0 + wn * 64 + nt * 8 + t * 2;   // even
                int h = col >> 6;
                int d0 = col & 63;
                float v0 = acc[mt][nt][half * 2 + 0];
                float v1 = acc[mt][nt][half * 2 + 1];
                float o0, o1;
                if (mode == 3) {
                    o0 = v0; o1 = v1;
                } else {
                    int j0 = d0 & 31, j1 = (d0 + 1) & 31;
                    float2 cs0 = *(const float2*)&g_rope[((size_t)sp * 32 + j0) * 2];
                    float2 cs1 = *(const float2*)&g_rope[((size_t)sp * 32 + j1) * 2];
                    o0 = v0 * cs0.x - v1 * cs0.y;
                    o1 = v1 * cs1.x + v0 * cs1.y;
                }
                float* dst;
                if (mode == 1)
                    dst = &g_q[(((size_t)b * NUM_HEADS + h) * SEQ + sp) * HD + d0];
                else if (mode == 2)
                    dst = &g_k[(((size_t)b * NUM_KV + h) * SEQ + sp) * HD + d0];
                else
                    dst = &g_v[(((size_t)b * NUM_KV + h) * SEQ + sp) * HD + d0];
                *(float2*)dst = make_float2(o0, o1);
            }
        }
    }
}

// ---------------------------------------------------------------------------
// Flash attention: 64x64 tiles, fp32, online softmax. P aliased onto K smem
// (48KB total -> 4 CTAs/SM with launch_bounds(256,4)).
// ---------------------------------------------------------------------------
__global__ __launch_bounds__(256, 4) void flash_attn()
{
    extern __shared__ float sm[];
    float* q_s = sm;             // [64][64]  d-major
    float* k_s = sm + 4096;      // [64][64]  d-major; reused as P [64][64] row-major
    float* v_s = sm + 8192;      // [64][64]  key-major

    const int tid = threadIdx.x;
    const int ty = tid >> 4;
    const int tx = tid & 15;
    const int qs = blockIdx.x * 64;
    const int h  = blockIdx.y;
    const int b  = blockIdx.z;
    const int kvh = h >> 2;

    const float* qg = &g_q[(((size_t)b * NUM_HEADS + h) * SEQ + qs) * HD];
    const float* kg = &g_k[(((size_t)b * NUM_KV + kvh) * SEQ) * HD];
    const float* vg = &g_v[(((size_t)b * NUM_KV + kvh) * SEQ) * HD];

    // Load Q tile, transposed to d-major
    {
        int r = tid >> 2;
        int c = (tid & 3) * 16;
#pragma unroll
        for (int u = 0; u < 4; u++) {
            float4 v4 = *(const float4*)&qg[r * 64 + c + u * 4];
            q_s[(c + u * 4 + 0) * 64 + r] = v4.x;
            q_s[(c + u * 4 + 1) * 64 + r] = v4.y;
            q_s[(c + u * 4 + 2) * 64 + r] = v4.z;
            q_s[(c + u * 4 + 3) * 64 + r] = v4.w;
        }
    }

    float m_i[4], l_i[4], acc[4][4];
#pragma unroll
    for (int i = 0; i < 4; i++) {
        m_i[i] = -1e30f;
        l_i[i] = 0.f;
#pragma unroll
        for (int j = 0; j < 4; j++) acc[i][j] = 0.f;
    }

    const float scale = 0.125f;

    for (int kt = 0; kt <= qs; kt += 64) {
        __syncthreads();  // prior PV reads (v_s, P=k_s) done; q_s visible on iter 0
        {
            int r = tid >> 2;
            int c = (tid & 3) * 16;
#pragma unroll
            for (int u = 0; u < 4; u++) {
                float4 kv4 = *(const float4*)&kg[(size_t)(kt + r) * 64 + c + u * 4];
                k_s[(c + u * 4 + 0) * 64 + r] = kv4.x;
                k_s[(c + u * 4 + 1) * 64 + r] = kv4.y;
                k_s[(c + u * 4 + 2) * 64 + r] = kv4.z;
                k_s[(c + u * 4 + 3) * 64 + r] = kv4.w;
                float4 vv4 = *(const float4*)&vg[(size_t)(kt + r) * 64 + c + u * 4];
                *(float4*)&v_s[r * 64 + c + u * 4] = vv4;
            }
        }
        __syncthreads();

        // S = Q @ K^T
        float sreg[4][4];
#pragma unroll
        for (int i = 0; i < 4; i++)
#pragma unroll
            for (int j = 0; j < 4; j++) sreg[i][j] = 0.f;

#pragma unroll 16
        for (int kd = 0; kd < 64; kd++) {
            float4 qf = *(float4*)&q_s[kd * 64 + ty * 4];
            float4 kf = *(float4*)&k_s[kd * 64 + tx * 4];
            float qa[4] = {qf.x, qf.y, qf.z, qf.w};
            float ka[4] = {kf.x, kf.y, kf.z, kf.w};
#pragma unroll
            for (int i = 0; i < 4; i++)
#pragma unroll
                for (int j = 0; j < 4; j++)
                    sreg[i][j] = fmaf(qa[i], ka[j], sreg[i][j]);
        }

        __syncthreads();  // all S reads of k_s done before P overwrites it

        // scale + causal mask
#pragma unroll
        for (int i = 0; i < 4; i++) {
            int row = qs + ty * 4 + i;
#pragma unroll
            for (int j = 0; j < 4; j++) {
                int col = kt + tx * 4 + j;
                float v = sreg[i][j] * scale;
                sreg[i][j] = (col > row) ? -1e30f : v;
            }
        }

        // online softmax, write P into k_s region
#pragma unroll
        for (int i = 0; i < 4; i++) {
            float mx = fmaxf(fmaxf(sreg[i][0], sreg[i][1]),
                             fmaxf(sreg[i][2], sreg[i][3]));
#pragma unroll
            for (int off = 8; off >= 1; off >>= 1)
                mx = fmaxf(mx, __shfl_xor_sync(0xffffffffu, mx, off));
            float mnew = fmaxf(m_i[i], mx);
            float alpha = __expf(m_i[i] - mnew);
            float ps = 0.f;
#pragma unroll
            for (int j = 0; j < 4; j++) {
                float p = __expf(sreg[i][j] - mnew);
                sreg[i][j] = p;
                ps += p;
            }
#pragma unroll
            for (int off = 8; off >= 1; off >>= 1)
                ps += __shfl_xor_sync(0xffffffffu, ps, off);
            l_i[i] = l_i[i] * alpha + ps;
            m_i[i] = mnew;
#pragma unroll
            for (int j = 0; j < 4; j++) acc[i][j] *= alpha;
            *(float4*)&k_s[(ty * 4 + i) * 64 + tx * 4] =
                make_float4(sreg[i][0], sreg[i][1], sreg[i][2], sreg[i][3]);
        }
        __syncthreads();

        // O += P @ V   (P lives in k_s)
#pragma unroll 8
        for (int kk = 0; kk < 64; kk++) {
            float4 vf = *(float4*)&v_s[kk * 64 + tx * 4];
#pragma unroll
            for (int i = 0; i < 4; i++) {
                float p = k_s[(ty * 4 + i) * 64 + kk];
                acc[i][0] = fmaf(p, vf.x, acc[i][0]);
                acc[i][1] = fmaf(p, vf.y, acc[i][1]);
                acc[i][2] = fmaf(p, vf.z, acc[i][2]);
                acc[i][3] = fmaf(p, vf.w, acc[i][3]);
            }
        }
    }

    float* og = &g_ao[((size_t)b * SEQ + qs) * DM + h * HD];
#pragma unroll
    for (int i = 0; i < 4; i++) {
        float inv = 1.f / l_i[i];
        float4 o = make_float4(acc[i][0] * inv, acc[i][1] * inv,
                               acc[i][2] * inv, acc[i][3] * inv);
        *(float4*)&og[(size_t)(ty * 4 + i) * DM + tx * 4] = o;
    }
}

// ---------------------------------------------------------------------------

extern "C" void kernel_launch(void* const* d_in, const int* in_sizes, int n_in,
                              void* d_out, int out_size)
{
    const float* x  = (const float*)d_in[0];
    const float* Wq = (const float*)d_in[2];
    const float* Wk = (const float*)d_in[3];
    const float* Wv = (const float*)d_in[4];
    const float* Wo = (const float*)d_in[5];
    float* out = (float*)d_out;

    const int M = B_DIM * SEQ;  // 4096

    cudaFuncSetAttribute(flash_attn, cudaFuncAttributeMaxDynamicSharedMemorySize,
                         48 * 1024);

    rope_init<<<(SEQ * 32) / 256, 256>>>();

    gemm_tc<<<dim3(DM / 128, M / 128), 128>>>(x, Wq, nullptr, M, DM, DM, 1);
    gemm_tc<<<dim3((NUM_KV * HD) / 128, M / 128), 128>>>(x, Wk, nullptr, M, NUM_KV * HD, DM, 2);
    gemm_tc<<<dim3((NUM_KV * HD) / 128, M / 128), 128>>>(x, Wv, nullptr, M, NUM_KV * HD, DM, 3);

    flash_attn<<<dim3(SEQ / 64, NUM_HEADS, B_DIM), 256, 48 * 1024>>>();

    void* aoPtr = nullptr;
    cudaGetSymbolAddress(&aoPtr, g_ao);
    gemm_tc<<<dim3(DM / 128, M / 128), 128>>>((const float*)aoPtr, Wo, out, M, DM, DM, 0);
}